// round 8
// baseline (speedup 1.0000x reference)
#include <cuda_runtime.h>
#include <math.h>

// ---------------- Config ----------------
#define BATCH 8
#define CCH   3
#define IMG   384
#define PCH   16
#define GH    24
#define GW    24
#define NP    576           // patches
#define NTOK  577           // +CLS
#define DMODEL 768
#define NHEAD 12
#define HD    64
#define LYRS  12
#define MLPD  3072
#define NCLS  1000

#define TOKS  (BATCH*NTOK)          // 4616
#define PROWS (BATCH*NP)            // 4608
#define SP    592                   // padded S row stride (577 -> 592, mult of 16)

typedef unsigned long long ull;

// ---------------- Scratch (static device globals; no runtime alloc) ----------------
__device__ float g_T[PROWS*DMODEL];      // gathered patch pixels
__device__ float g_E[PROWS*DMODEL];      // patch embeddings
__device__ float g_H[TOKS*DMODEL];       // residual stream
__device__ float g_Y[TOKS*DMODEL];       // LN output
__device__ float g_Q[TOKS*DMODEL];
__device__ float g_K[TOKS*DMODEL];
__device__ float g_V[TOKS*DMODEL];
__device__ float g_O[TOKS*DMODEL];
__device__ float g_S[(size_t)BATCH*NHEAD*NTOK*SP];   // attn probs (padded rows)
__device__ float g_M[(size_t)TOKS*MLPD];             // MLP hidden

// ---------------- f32x2 helpers (sm_103a packed fp32) ----------------
__device__ __forceinline__ ull pack2(float x) {
    ull r;
    unsigned u = __float_as_uint(x);
    asm("mov.b64 %0, {%1, %1};" : "=l"(r) : "r"(u));
    return r;
}
__device__ __forceinline__ void fma2(ull& d, ull a, ull b) {
    asm("fma.rn.f32x2 %0, %1, %2, %0;" : "+l"(d) : "l"(a), "l"(b));
}
__device__ __forceinline__ float2 unpack2(ull v) {
    float2 f;
    asm("mov.b64 {%0, %1}, %2;" : "=f"(f.x), "=f"(f.y) : "l"(v));
    return f;
}

__device__ __forceinline__ float gelu_exact(float x) {
    return 0.5f * x * (1.0f + erff(x * 0.70710678118654752f));
}

// ---------------- Generic GEMM: C = A[MxK] @ B[KxN] + bias (+act) (+res) ----------------
// BM=128, BN=128, BK=16, 256 threads, 8x8 per thread, f32x2 packed FMA.
// Requires: K % 16 == 0, N % 128 == 0. M guarded.
__global__ __launch_bounds__(256, 2) void gemm_kernel(
    const float* __restrict__ A, const float* __restrict__ B,
    const float* __restrict__ bias, const float* __restrict__ res,
    float* __restrict__ C, int M, int N, int K, int act)
{
    __shared__ float As[16][128];   // transposed: As[k][m]
    __shared__ float Bs[16][128];   // Bs[k][n]

    const int bm = blockIdx.y * 128;
    const int bn = blockIdx.x * 128;
    const int tid = threadIdx.x;
    const int ty = tid >> 4, tx = tid & 15;
    const int row0 = ty * 8, col0 = tx * 8;

    ull acc[8][4];
#pragma unroll
    for (int i = 0; i < 8; i++)
#pragma unroll
        for (int j = 0; j < 4; j++) acc[i][j] = 0ULL;

    for (int k0 = 0; k0 < K; k0 += 16) {
#pragma unroll
        for (int i = 0; i < 2; i++) {
            int idx = tid + i * 256;                 // 0..511
            // A tile: 128 rows x 16 k (as 4 float4 per row)
            int r  = idx >> 2;
            int kq = (idx & 3) * 4;
            float4 va = make_float4(0.f, 0.f, 0.f, 0.f);
            if (bm + r < M) va = *(const float4*)(A + (size_t)(bm + r) * K + k0 + kq);
            As[kq + 0][r] = va.x; As[kq + 1][r] = va.y;
            As[kq + 2][r] = va.z; As[kq + 3][r] = va.w;
            // B tile: 16 k x 128 n
            int kk = idx >> 5;
            int nq = (idx & 31) * 4;
            *(float4*)&Bs[kk][nq] =
                *(const float4*)(B + (size_t)(k0 + kk) * N + bn + nq);
        }
        __syncthreads();

#pragma unroll
        for (int k = 0; k < 16; k++) {
            float4 a0 = *(const float4*)&As[k][row0];
            float4 a1 = *(const float4*)&As[k][row0 + 4];
            ull a2r[8];
            a2r[0] = pack2(a0.x); a2r[1] = pack2(a0.y);
            a2r[2] = pack2(a0.z); a2r[3] = pack2(a0.w);
            a2r[4] = pack2(a1.x); a2r[5] = pack2(a1.y);
            a2r[6] = pack2(a1.z); a2r[7] = pack2(a1.w);
            ull b2[4];
            b2[0] = *(const ull*)&Bs[k][col0 + 0];
            b2[1] = *(const ull*)&Bs[k][col0 + 2];
            b2[2] = *(const ull*)&Bs[k][col0 + 4];
            b2[3] = *(const ull*)&Bs[k][col0 + 6];
#pragma unroll
            for (int i = 0; i < 8; i++)
#pragma unroll
                for (int j = 0; j < 4; j++) fma2(acc[i][j], a2r[i], b2[j]);
        }
        __syncthreads();
    }

#pragma unroll
    for (int i = 0; i < 8; i++) {
        int gr = bm + row0 + i;
        if (gr >= M) continue;
        float* crow = C + (size_t)gr * N + bn + col0;
        const float* rrow = res ? (res + (size_t)gr * N + bn + col0) : (const float*)0;
#pragma unroll
        for (int j = 0; j < 4; j++) {
            float2 v = unpack2(acc[i][j]);
            int c = 2 * j;
            float x0 = v.x + bias[bn + col0 + c];
            float x1 = v.y + bias[bn + col0 + c + 1];
            if (act == 1) { x0 = gelu_exact(x0); x1 = gelu_exact(x1); }
            if (rrow) { x0 += rrow[c]; x1 += rrow[c + 1]; }
            crow[c] = x0; crow[c + 1] = x1;
        }
    }
}

// ---------------- Patch gather (faithful buggy flattening) ----------------
// out linear index l over [PROWS*768]:
//   p1 = l / 221184; rem = l % 221184; m = rem/16; p2 = rem%16
//   b = m/1728; c = (m/576)%3; gh = (m/24)%24; gw = m%24
//   val = x[b, c, gh*16+p1, gw*16+p2]
__global__ void patch_gather_kernel(const float* __restrict__ x, float* __restrict__ T)
{
    int idx = blockIdx.x * blockDim.x + threadIdx.x;
    if (idx >= PROWS * DMODEL) return;
    int p1  = idx / 221184;
    int rem = idx % 221184;
    int m   = rem >> 4;
    int p2  = rem & 15;
    int b   = m / 1728;
    int mm  = m - b * 1728;
    int c   = mm / 576;
    int mg  = mm - c * 576;
    int gh  = mg / 24;
    int gw  = mg - gh * 24;
    T[idx] = x[(((size_t)(b * CCH + c) * IMG) + gh * 16 + p1) * IMG + gw * 16 + p2];
}

// ---------------- Assemble tokens: CLS + patches + pos_emb ----------------
__global__ void assemble_kernel(const float* __restrict__ E, const float* __restrict__ cls,
                                const float* __restrict__ pos, float* __restrict__ H)
{
    int idx = blockIdx.x * blockDim.x + threadIdx.x;
    if (idx >= TOKS * DMODEL) return;
    int tok = idx / DMODEL;
    int k   = idx - tok * DMODEL;
    int b   = tok / NTOK;
    int n   = tok - b * NTOK;
    float v = (n == 0) ? cls[k] : E[((size_t)(b * NP + n - 1)) * DMODEL + k];
    H[idx] = v + pos[(size_t)n * DMODEL + k];
}

// ---------------- LayerNorm (row per block, 768 = 3*256) ----------------
__global__ void layernorm_kernel(const float* __restrict__ X, const float* __restrict__ g,
                                 const float* __restrict__ bta, float* __restrict__ Y)
{
    int r = blockIdx.x;
    const float* xr = X + (size_t)r * DMODEL;
    float* yr = Y + (size_t)r * DMODEL;
    int tid = threadIdx.x;
    float v0 = xr[tid], v1 = xr[tid + 256], v2 = xr[tid + 512];
    float s  = v0 + v1 + v2;
    float s2 = v0 * v0 + v1 * v1 + v2 * v2;
#pragma unroll
    for (int o = 16; o; o >>= 1) {
        s  += __shfl_xor_sync(0xffffffffu, s,  o);
        s2 += __shfl_xor_sync(0xffffffffu, s2, o);
    }
    __shared__ float r1[8], r2[8];
    if ((tid & 31) == 0) { r1[tid >> 5] = s; r2[tid >> 5] = s2; }
    __syncthreads();
    float S = 0.f, S2 = 0.f;
#pragma unroll
    for (int w = 0; w < 8; w++) { S += r1[w]; S2 += r2[w]; }
    float mean = S * (1.0f / 768.0f);
    float var  = S2 * (1.0f / 768.0f) - mean * mean;
    float inv  = rsqrtf(var + 1e-5f);
    yr[tid]       = (v0 - mean) * inv * g[tid]       + bta[tid];
    yr[tid + 256] = (v1 - mean) * inv * g[tid + 256] + bta[tid + 256];
    yr[tid + 512] = (v2 - mean) * inv * g[tid + 512] + bta[tid + 512];
}

// ---------------- Attention scores: S[bh] = scale * Q_bh @ K_bh^T ----------------
// grid (10, 10, 96), 256 threads, 64x64 tile, 4x4 per thread.
__global__ __launch_bounds__(256) void attn_scores_kernel(
    const float* __restrict__ Q, const float* __restrict__ K, float* __restrict__ S)
{
    const int bh = blockIdx.z;
    const int b = bh / NHEAD, h = bh - b * NHEAD;
    const float* Qb = Q + (size_t)b * NTOK * DMODEL + h * HD;
    const float* Kb = K + (size_t)b * NTOK * DMODEL + h * HD;
    float* Sb = S + (size_t)bh * NTOK * SP;
    const int m0 = blockIdx.y * 64, n0 = blockIdx.x * 64;

    __shared__ float Qs[64][68];
    __shared__ float Ks[64][68];
    const int tid = threadIdx.x;

#pragma unroll
    for (int i = 0; i < 4; i++) {
        int f4 = tid + i * 256;          // 0..1023
        int r  = f4 >> 4;
        int d4 = (f4 & 15) * 4;
        float4 q = make_float4(0.f, 0.f, 0.f, 0.f), kv = q;
        if (m0 + r < NTOK) q  = *(const float4*)(Qb + (size_t)(m0 + r) * DMODEL + d4);
        if (n0 + r < NTOK) kv = *(const float4*)(Kb + (size_t)(n0 + r) * DMODEL + d4);
        *(float4*)&Qs[r][d4] = q;
        *(float4*)&Ks[r][d4] = kv;
    }
    __syncthreads();

    const int ty = tid >> 4, tx = tid & 15;
    float acc[4][4] = {};
#pragma unroll
    for (int d4 = 0; d4 < 16; d4++) {
        float4 a[4], bb[4];
#pragma unroll
        for (int i = 0; i < 4; i++) a[i]  = *(const float4*)&Qs[ty * 4 + i][d4 * 4];
#pragma unroll
        for (int j = 0; j < 4; j++) bb[j] = *(const float4*)&Ks[tx * 4 + j][d4 * 4];
#pragma unroll
        for (int i = 0; i < 4; i++)
#pragma unroll
            for (int j = 0; j < 4; j++)
                acc[i][j] += a[i].x * bb[j].x + a[i].y * bb[j].y
                           + a[i].z * bb[j].z + a[i].w * bb[j].w;
    }
    const float scale = 0.125f;  // 1/sqrt(64)
#pragma unroll
    for (int i = 0; i < 4; i++) {
        int m = m0 + ty * 4 + i;
        if (m >= NTOK) continue;
#pragma unroll
        for (int j = 0; j < 4; j++) {
            int n = n0 + tx * 4 + j;
            if (n < NTOK) Sb[(size_t)m * SP + n] = acc[i][j] * scale;
        }
    }
}

// ---------------- Row softmax over S (also zeroes pad cols 577..591) ----------------
__global__ void softmax_kernel(float* __restrict__ S)
{
    int r  = blockIdx.x;                    // 0..96*577-1
    int bh = r / NTOK, m = r - bh * NTOK;
    float* row = S + (size_t)bh * NTOK * SP + (size_t)m * SP;
    int tid = threadIdx.x;                  // 128

    float lmax = -3.4e38f;
    for (int c = tid; c < NTOK; c += 128) lmax = fmaxf(lmax, row[c]);
#pragma unroll
    for (int o = 16; o; o >>= 1) lmax = fmaxf(lmax, __shfl_xor_sync(0xffffffffu, lmax, o));
    __shared__ float sred[4];
    if ((tid & 31) == 0) sred[tid >> 5] = lmax;
    __syncthreads();
    float bmax = fmaxf(fmaxf(sred[0], sred[1]), fmaxf(sred[2], sred[3]));
    __syncthreads();

    float lsum = 0.f;
    for (int c = tid; c < NTOK; c += 128) {
        float e = expf(row[c] - bmax);
        row[c] = e;
        lsum += e;
    }
#pragma unroll
    for (int o = 16; o; o >>= 1) lsum += __shfl_xor_sync(0xffffffffu, lsum, o);
    if ((tid & 31) == 0) sred[tid >> 5] = lsum;
    __syncthreads();
    float inv = 1.0f / (sred[0] + sred[1] + sred[2] + sred[3]);
    for (int c = tid; c < NTOK; c += 128) row[c] *= inv;
    if (tid < SP - NTOK) row[NTOK + tid] = 0.0f;
}

// ---------------- Attention output: O_bh = P_bh @ V_bh ----------------
// grid (1, 10, 96); block 256; 64 rows x 64 cols per block; K tiled by 16 over padded SP.
__global__ __launch_bounds__(256) void attn_out_kernel(
    const float* __restrict__ S, const float* __restrict__ V, float* __restrict__ O)
{
    const int bh = blockIdx.z;
    const int b = bh / NHEAD, h = bh - b * NHEAD;
    const float* Sb = S + (size_t)bh * NTOK * SP;
    const float* Vb = V + (size_t)b * NTOK * DMODEL + h * HD;
    float* Ob = O + (size_t)b * NTOK * DMODEL + h * HD;
    const int m0 = blockIdx.y * 64;

    __shared__ float Ps[64][20];
    __shared__ float Vs[16][64];
    const int tid = threadIdx.x;
    const int ty = tid >> 4, tx = tid & 15;

    float acc[4][4] = {};
    for (int k0 = 0; k0 < SP; k0 += 16) {
        {   // P tile: 64 x 16
            int r  = tid >> 2;
            int k4 = (tid & 3) * 4;
            float4 p = make_float4(0.f, 0.f, 0.f, 0.f);
            if (m0 + r < NTOK) p = *(const float4*)(Sb + (size_t)(m0 + r) * SP + k0 + k4);
            *(float4*)&Ps[r][k4] = p;
        }
        {   // V tile: 16 x 64
            int kk = tid >> 4;
            int n4 = (tid & 15) * 4;
            float4 v = make_float4(0.f, 0.f, 0.f, 0.f);
            if (k0 + kk < NTOK) v = *(const float4*)(Vb + (size_t)(k0 + kk) * DMODEL + n4);
            *(float4*)&Vs[kk][n4] = v;
        }
        __syncthreads();
#pragma unroll
        for (int kk = 0; kk < 16; kk++) {
            float4 bv = *(const float4*)&Vs[kk][tx * 4];
            float a0 = Ps[ty * 4 + 0][kk];
            float a1 = Ps[ty * 4 + 1][kk];
            float a2 = Ps[ty * 4 + 2][kk];
            float a3 = Ps[ty * 4 + 3][kk];
            acc[0][0] += a0 * bv.x; acc[0][1] += a0 * bv.y; acc[0][2] += a0 * bv.z; acc[0][3] += a0 * bv.w;
            acc[1][0] += a1 * bv.x; acc[1][1] += a1 * bv.y; acc[1][2] += a1 * bv.z; acc[1][3] += a1 * bv.w;
            acc[2][0] += a2 * bv.x; acc[2][1] += a2 * bv.y; acc[2][2] += a2 * bv.z; acc[2][3] += a2 * bv.w;
            acc[3][0] += a3 * bv.x; acc[3][1] += a3 * bv.y; acc[3][2] += a3 * bv.z; acc[3][3] += a3 * bv.w;
        }
        __syncthreads();
    }
#pragma unroll
    for (int i = 0; i < 4; i++) {
        int m = m0 + ty * 4 + i;
        if (m >= NTOK) continue;
        float4 o4 = make_float4(acc[i][0], acc[i][1], acc[i][2], acc[i][3]);
        *(float4*)(Ob + (size_t)m * DMODEL + tx * 4) = o4;
    }
}

// ---------------- Classifier head (CLS token) ----------------
__global__ void head_kernel(const float* __restrict__ Hln, const float* __restrict__ W,
                            const float* __restrict__ bias, float* __restrict__ out)
{
    int idx = blockIdx.x * blockDim.x + threadIdx.x;
    if (idx >= BATCH * NCLS) return;
    int b = idx / NCLS, c = idx - b * NCLS;
    const float* hr = Hln + (size_t)b * NTOK * DMODEL;   // row 0 = CLS
    float s = bias[c];
#pragma unroll 4
    for (int d = 0; d < DMODEL; d++) s += hr[d] * W[(size_t)d * NCLS + c];
    out[idx] = s;
}

// ---------------- Host orchestration ----------------
extern "C" void kernel_launch(void* const* d_in, const int* in_sizes, int n_in,
                              void* d_out, int out_size)
{
    (void)in_sizes; (void)n_in; (void)out_size;
    const float* x      = (const float*)d_in[0];
    const float* proj_w = (const float*)d_in[1];
    const float* proj_b = (const float*)d_in[2];
    const float* cls_e  = (const float*)d_in[3];
    const float* pos_e  = (const float*)d_in[4];
    const float* ln1_g  = (const float*)d_in[5];
    const float* ln1_b  = (const float*)d_in[6];
    const float* qw     = (const float*)d_in[7];
    const float* qb     = (const float*)d_in[8];
    const float* kw     = (const float*)d_in[9];
    const float* kb     = (const float*)d_in[10];
    const float* vw     = (const float*)d_in[11];
    const float* vb     = (const float*)d_in[12];
    const float* ow     = (const float*)d_in[13];
    const float* ob     = (const float*)d_in[14];
    const float* ln2_g  = (const float*)d_in[15];
    const float* ln2_b  = (const float*)d_in[16];
    const float* fcw    = (const float*)d_in[17];
    const float* fcb    = (const float*)d_in[18];
    const float* pw     = (const float*)d_in[19];
    const float* pb     = (const float*)d_in[20];
    const float* lnf_g  = (const float*)d_in[21];
    const float* lnf_b  = (const float*)d_in[22];
    const float* head_w = (const float*)d_in[23];
    const float* head_b = (const float*)d_in[24];

    float *T, *E, *H, *Y, *Q, *Kp, *V, *O, *S, *Mm;
    cudaGetSymbolAddress((void**)&T,  g_T);
    cudaGetSymbolAddress((void**)&E,  g_E);
    cudaGetSymbolAddress((void**)&H,  g_H);
    cudaGetSymbolAddress((void**)&Y,  g_Y);
    cudaGetSymbolAddress((void**)&Q,  g_Q);
    cudaGetSymbolAddress((void**)&Kp, g_K);
    cudaGetSymbolAddress((void**)&V,  g_V);
    cudaGetSymbolAddress((void**)&O,  g_O);
    cudaGetSymbolAddress((void**)&S,  g_S);
    cudaGetSymbolAddress((void**)&Mm, g_M);

    // Patch embed
    patch_gather_kernel<<<(PROWS * DMODEL + 255) / 256, 256>>>(x, T);
    gemm_kernel<<<dim3(DMODEL / 128, PROWS / 128), 256>>>(
        T, proj_w, proj_b, (const float*)0, E, PROWS, DMODEL, DMODEL, 0);
    assemble_kernel<<<(TOKS * DMODEL + 255) / 256, 256>>>(E, cls_e, pos_e, H);

    const int MG = (TOKS + 127) / 128;   // 37
    for (int l = 0; l < LYRS; l++) {
        const size_t wo  = (size_t)l * DMODEL * DMODEL;
        const size_t bo  = (size_t)l * DMODEL;
        const size_t fwo = (size_t)l * DMODEL * MLPD;
        const size_t fbo = (size_t)l * MLPD;

        layernorm_kernel<<<TOKS, 256>>>(H, ln1_g + bo, ln1_b + bo, Y);
        gemm_kernel<<<dim3(6, MG), 256>>>(Y, qw + wo, qb + bo, (const float*)0, Q,  TOKS, DMODEL, DMODEL, 0);
        gemm_kernel<<<dim3(6, MG), 256>>>(Y, kw + wo, kb + bo, (const float*)0, Kp, TOKS, DMODEL, DMODEL, 0);
        gemm_kernel<<<dim3(6, MG), 256>>>(Y, vw + wo, vb + bo, (const float*)0, V,  TOKS, DMODEL, DMODEL, 0);

        attn_scores_kernel<<<dim3(10, 10, BATCH * NHEAD), 256>>>(Q, Kp, S);
        softmax_kernel<<<BATCH * NHEAD * NTOK, 128>>>(S);
        attn_out_kernel<<<dim3(1, 10, BATCH * NHEAD), 256>>>(S, V, O);

        gemm_kernel<<<dim3(6, MG), 256>>>(O, ow + wo, ob + bo, H, H, TOKS, DMODEL, DMODEL, 0);

        layernorm_kernel<<<TOKS, 256>>>(H, ln2_g + bo, ln2_b + bo, Y);
        gemm_kernel<<<dim3(MLPD / 128, MG), 256>>>(Y, fcw + fwo, fcb + fbo, (const float*)0, Mm, TOKS, MLPD, DMODEL, 1);
        gemm_kernel<<<dim3(6, MG), 256>>>(Mm, pw + fwo, pb + bo, H, H, TOKS, DMODEL, MLPD, 0);
    }

    layernorm_kernel<<<TOKS, 256>>>(H, lnf_g, lnf_b, Y);
    head_kernel<<<(BATCH * NCLS + 255) / 256, 256>>>(Y, head_w, head_b, (float*)d_out);
}

// round 9
// speedup vs baseline: 1.0014x; 1.0014x over previous
#include <cuda_runtime.h>
#include <math.h>

// ---------------- Config ----------------
#define BATCH 8
#define CCH   3
#define IMG   384
#define PCH   16
#define GH    24
#define GW    24
#define NP    576           // patches
#define NTOK  577           // +CLS
#define DMODEL 768
#define NHEAD 12
#define HD    64
#define LYRS  12
#define MLPD  3072
#define NCLS  1000

#define TOKS  (BATCH*NTOK)          // 4616
#define PROWS (BATCH*NP)            // 4608
#define SP    592                   // padded S row stride (577 -> 592, mult of 16)

typedef unsigned long long ull;

// ---------------- Scratch (static device globals; no runtime alloc) ----------------
__device__ float g_T[PROWS*DMODEL];      // gathered patch pixels
__device__ float g_E[PROWS*DMODEL];      // patch embeddings
__device__ float g_H[TOKS*DMODEL];       // residual stream
__device__ float g_Y[TOKS*DMODEL];       // LN output
__device__ float g_Q[TOKS*DMODEL];
__device__ float g_K[TOKS*DMODEL];
__device__ float g_V[TOKS*DMODEL];
__device__ float g_O[TOKS*DMODEL];
__device__ float g_S[(size_t)BATCH*NHEAD*NTOK*SP];   // attn probs (padded rows)
__device__ float g_M[(size_t)TOKS*MLPD];             // MLP hidden

// ---------------- f32x2 helpers (sm_103a packed fp32) ----------------
__device__ __forceinline__ ull pack2(float x) {
    ull r;
    unsigned u = __float_as_uint(x);
    asm("mov.b64 %0, {%1, %1};" : "=l"(r) : "r"(u));
    return r;
}
__device__ __forceinline__ void fma2(ull& d, ull a, ull b) {
    asm("fma.rn.f32x2 %0, %1, %2, %0;" : "+l"(d) : "l"(a), "l"(b));
}
__device__ __forceinline__ float2 unpack2(ull v) {
    float2 f;
    asm("mov.b64 {%0, %1}, %2;" : "=f"(f.x), "=f"(f.y) : "l"(v));
    return f;
}

__device__ __forceinline__ float gelu_exact(float x) {
    return 0.5f * x * (1.0f + erff(x * 0.70710678118654752f));
}

// ---------------- Generic GEMM: C = A[MxK] @ B[KxN] + bias (+act) (+res) ----------------
// BM=128, BN=128, BK=16, 256 threads, 8x8 per thread, f32x2 packed FMA.
// Requires: K % 16 == 0, N % 128 == 0. M guarded.
__global__ __launch_bounds__(256, 2) void gemm_kernel(
    const float* __restrict__ A, const float* __restrict__ B,
    const float* __restrict__ bias, const float* __restrict__ res,
    float* __restrict__ C, int M, int N, int K, int act)
{
    __shared__ float As[16][128];   // transposed: As[k][m]
    __shared__ float Bs[16][128];   // Bs[k][n]

    const int bm = blockIdx.y * 128;
    const int bn = blockIdx.x * 128;
    const int tid = threadIdx.x;
    const int ty = tid >> 4, tx = tid & 15;
    const int row0 = ty * 8, col0 = tx * 8;

    ull acc[8][4];
#pragma unroll
    for (int i = 0; i < 8; i++)
#pragma unroll
        for (int j = 0; j < 4; j++) acc[i][j] = 0ULL;

    for (int k0 = 0; k0 < K; k0 += 16) {
#pragma unroll
        for (int i = 0; i < 2; i++) {
            int idx = tid + i * 256;                 // 0..511
            // A tile: 128 rows x 16 k (as 4 float4 per row)
            int r  = idx >> 2;
            int kq = (idx & 3) * 4;
            float4 va = make_float4(0.f, 0.f, 0.f, 0.f);
            if (bm + r < M) va = *(const float4*)(A + (size_t)(bm + r) * K + k0 + kq);
            As[kq + 0][r] = va.x; As[kq + 1][r] = va.y;
            As[kq + 2][r] = va.z; As[kq + 3][r] = va.w;
            // B tile: 16 k x 128 n
            int kk = idx >> 5;
            int nq = (idx & 31) * 4;
            *(float4*)&Bs[kk][nq] =
                *(const float4*)(B + (size_t)(k0 + kk) * N + bn + nq);
        }
        __syncthreads();

#pragma unroll
        for (int k = 0; k < 16; k++) {
            float4 a0 = *(const float4*)&As[k][row0];
            float4 a1 = *(const float4*)&As[k][row0 + 4];
            ull a2r[8];
            a2r[0] = pack2(a0.x); a2r[1] = pack2(a0.y);
            a2r[2] = pack2(a0.z); a2r[3] = pack2(a0.w);
            a2r[4] = pack2(a1.x); a2r[5] = pack2(a1.y);
            a2r[6] = pack2(a1.z); a2r[7] = pack2(a1.w);
            ull b2[4];
            b2[0] = *(const ull*)&Bs[k][col0 + 0];
            b2[1] = *(const ull*)&Bs[k][col0 + 2];
            b2[2] = *(const ull*)&Bs[k][col0 + 4];
            b2[3] = *(const ull*)&Bs[k][col0 + 6];
#pragma unroll
            for (int i = 0; i < 8; i++)
#pragma unroll
                for (int j = 0; j < 4; j++) fma2(acc[i][j], a2r[i], b2[j]);
        }
        __syncthreads();
    }

#pragma unroll
    for (int i = 0; i < 8; i++) {
        int gr = bm + row0 + i;
        if (gr >= M) continue;
        float* crow = C + (size_t)gr * N + bn + col0;
        const float* rrow = res ? (res + (size_t)gr * N + bn + col0) : (const float*)0;
#pragma unroll
        for (int j = 0; j < 4; j++) {
            float2 v = unpack2(acc[i][j]);
            int c = 2 * j;
            float x0 = v.x + bias[bn + col0 + c];
            float x1 = v.y + bias[bn + col0 + c + 1];
            if (act == 1) { x0 = gelu_exact(x0); x1 = gelu_exact(x1); }
            if (rrow) { x0 += rrow[c]; x1 += rrow[c + 1]; }
            crow[c] = x0; crow[c + 1] = x1;
        }
    }
}

// ---------------- Patch gather (faithful buggy flattening) ----------------
// out linear index l over [PROWS*768]:
//   p1 = l / 221184; rem = l % 221184; m = rem/16; p2 = rem%16
//   b = m/1728; c = (m/576)%3; gh = (m/24)%24; gw = m%24
//   val = x[b, c, gh*16+p1, gw*16+p2]
__global__ void patch_gather_kernel(const float* __restrict__ x, float* __restrict__ T)
{
    int idx = blockIdx.x * blockDim.x + threadIdx.x;
    if (idx >= PROWS * DMODEL) return;
    int p1  = idx / 221184;
    int rem = idx % 221184;
    int m   = rem >> 4;
    int p2  = rem & 15;
    int b   = m / 1728;
    int mm  = m - b * 1728;
    int c   = mm / 576;
    int mg  = mm - c * 576;
    int gh  = mg / 24;
    int gw  = mg - gh * 24;
    T[idx] = x[(((size_t)(b * CCH + c) * IMG) + gh * 16 + p1) * IMG + gw * 16 + p2];
}

// ---------------- Assemble tokens: CLS + patches + pos_emb ----------------
__global__ void assemble_kernel(const float* __restrict__ E, const float* __restrict__ cls,
                                const float* __restrict__ pos, float* __restrict__ H)
{
    int idx = blockIdx.x * blockDim.x + threadIdx.x;
    if (idx >= TOKS * DMODEL) return;
    int tok = idx / DMODEL;
    int k   = idx - tok * DMODEL;
    int b   = tok / NTOK;
    int n   = tok - b * NTOK;
    float v = (n == 0) ? cls[k] : E[((size_t)(b * NP + n - 1)) * DMODEL + k];
    H[idx] = v + pos[(size_t)n * DMODEL + k];
}

// ---------------- LayerNorm (row per block, 768 = 3*256) ----------------
__global__ void layernorm_kernel(const float* __restrict__ X, const float* __restrict__ g,
                                 const float* __restrict__ bta, float* __restrict__ Y)
{
    int r = blockIdx.x;
    const float* xr = X + (size_t)r * DMODEL;
    float* yr = Y + (size_t)r * DMODEL;
    int tid = threadIdx.x;
    float v0 = xr[tid], v1 = xr[tid + 256], v2 = xr[tid + 512];
    float s  = v0 + v1 + v2;
    float s2 = v0 * v0 + v1 * v1 + v2 * v2;
#pragma unroll
    for (int o = 16; o; o >>= 1) {
        s  += __shfl_xor_sync(0xffffffffu, s,  o);
        s2 += __shfl_xor_sync(0xffffffffu, s2, o);
    }
    __shared__ float r1[8], r2[8];
    if ((tid & 31) == 0) { r1[tid >> 5] = s; r2[tid >> 5] = s2; }
    __syncthreads();
    float S = 0.f, S2 = 0.f;
#pragma unroll
    for (int w = 0; w < 8; w++) { S += r1[w]; S2 += r2[w]; }
    float mean = S * (1.0f / 768.0f);
    float var  = S2 * (1.0f / 768.0f) - mean * mean;
    float inv  = rsqrtf(var + 1e-5f);
    yr[tid]       = (v0 - mean) * inv * g[tid]       + bta[tid];
    yr[tid + 256] = (v1 - mean) * inv * g[tid + 256] + bta[tid + 256];
    yr[tid + 512] = (v2 - mean) * inv * g[tid + 512] + bta[tid + 512];
}

// ---------------- Attention scores: S[bh] = scale * Q_bh @ K_bh^T ----------------
// grid (10, 10, 96), 256 threads, 64x64 tile, 4x4 per thread.
__global__ __launch_bounds__(256) void attn_scores_kernel(
    const float* __restrict__ Q, const float* __restrict__ K, float* __restrict__ S)
{
    const int bh = blockIdx.z;
    const int b = bh / NHEAD, h = bh - b * NHEAD;
    const float* Qb = Q + (size_t)b * NTOK * DMODEL + h * HD;
    const float* Kb = K + (size_t)b * NTOK * DMODEL + h * HD;
    float* Sb = S + (size_t)bh * NTOK * SP;
    const int m0 = blockIdx.y * 64, n0 = blockIdx.x * 64;

    __shared__ float Qs[64][68];
    __shared__ float Ks[64][68];
    const int tid = threadIdx.x;

#pragma unroll
    for (int i = 0; i < 4; i++) {
        int f4 = tid + i * 256;          // 0..1023
        int r  = f4 >> 4;
        int d4 = (f4 & 15) * 4;
        float4 q = make_float4(0.f, 0.f, 0.f, 0.f), kv = q;
        if (m0 + r < NTOK) q  = *(const float4*)(Qb + (size_t)(m0 + r) * DMODEL + d4);
        if (n0 + r < NTOK) kv = *(const float4*)(Kb + (size_t)(n0 + r) * DMODEL + d4);
        *(float4*)&Qs[r][d4] = q;
        *(float4*)&Ks[r][d4] = kv;
    }
    __syncthreads();

    const int ty = tid >> 4, tx = tid & 15;
    float acc[4][4] = {};
#pragma unroll
    for (int d4 = 0; d4 < 16; d4++) {
        float4 a[4], bb[4];
#pragma unroll
        for (int i = 0; i < 4; i++) a[i]  = *(const float4*)&Qs[ty * 4 + i][d4 * 4];
#pragma unroll
        for (int j = 0; j < 4; j++) bb[j] = *(const float4*)&Ks[tx * 4 + j][d4 * 4];
#pragma unroll
        for (int i = 0; i < 4; i++)
#pragma unroll
            for (int j = 0; j < 4; j++)
                acc[i][j] += a[i].x * bb[j].x + a[i].y * bb[j].y
                           + a[i].z * bb[j].z + a[i].w * bb[j].w;
    }
    const float scale = 0.125f;  // 1/sqrt(64)
#pragma unroll
    for (int i = 0; i < 4; i++) {
        int m = m0 + ty * 4 + i;
        if (m >= NTOK) continue;
#pragma unroll
        for (int j = 0; j < 4; j++) {
            int n = n0 + tx * 4 + j;
            if (n < NTOK) Sb[(size_t)m * SP + n] = acc[i][j] * scale;
        }
    }
}

// ---------------- Row softmax over S (also zeroes pad cols 577..591) ----------------
__global__ void softmax_kernel(float* __restrict__ S)
{
    int r  = blockIdx.x;                    // 0..96*577-1
    int bh = r / NTOK, m = r - bh * NTOK;
    float* row = S + (size_t)bh * NTOK * SP + (size_t)m * SP;
    int tid = threadIdx.x;                  // 128

    float lmax = -3.4e38f;
    for (int c = tid; c < NTOK; c += 128) lmax = fmaxf(lmax, row[c]);
#pragma unroll
    for (int o = 16; o; o >>= 1) lmax = fmaxf(lmax, __shfl_xor_sync(0xffffffffu, lmax, o));
    __shared__ float sred[4];
    if ((tid & 31) == 0) sred[tid >> 5] = lmax;
    __syncthreads();
    float bmax = fmaxf(fmaxf(sred[0], sred[1]), fmaxf(sred[2], sred[3]));
    __syncthreads();

    float lsum = 0.f;
    for (int c = tid; c < NTOK; c += 128) {
        float e = expf(row[c] - bmax);
        row[c] = e;
        lsum += e;
    }
#pragma unroll
    for (int o = 16; o; o >>= 1) lsum += __shfl_xor_sync(0xffffffffu, lsum, o);
    if ((tid & 31) == 0) sred[tid >> 5] = lsum;
    __syncthreads();
    float inv = 1.0f / (sred[0] + sred[1] + sred[2] + sred[3]);
    for (int c = tid; c < NTOK; c += 128) row[c] *= inv;
    if (tid < SP - NTOK) row[NTOK + tid] = 0.0f;
}

// ---------------- Attention output: O_bh = P_bh @ V_bh ----------------
// grid (1, 10, 96); block 256; 64 rows x 64 cols per block; K tiled by 16 over padded SP.
__global__ __launch_bounds__(256) void attn_out_kernel(
    const float* __restrict__ S, const float* __restrict__ V, float* __restrict__ O)
{
    const int bh = blockIdx.z;
    const int b = bh / NHEAD, h = bh - b * NHEAD;
    const float* Sb = S + (size_t)bh * NTOK * SP;
    const float* Vb = V + (size_t)b * NTOK * DMODEL + h * HD;
    float* Ob = O + (size_t)b * NTOK * DMODEL + h * HD;
    const int m0 = blockIdx.y * 64;

    __shared__ float Ps[64][20];
    __shared__ float Vs[16][64];
    const int tid = threadIdx.x;
    const int ty = tid >> 4, tx = tid & 15;

    float acc[4][4] = {};
    for (int k0 = 0; k0 < SP; k0 += 16) {
        {   // P tile: 64 x 16
            int r  = tid >> 2;
            int k4 = (tid & 3) * 4;
            float4 p = make_float4(0.f, 0.f, 0.f, 0.f);
            if (m0 + r < NTOK) p = *(const float4*)(Sb + (size_t)(m0 + r) * SP + k0 + k4);
            *(float4*)&Ps[r][k4] = p;
        }
        {   // V tile: 16 x 64
            int kk = tid >> 4;
            int n4 = (tid & 15) * 4;
            float4 v = make_float4(0.f, 0.f, 0.f, 0.f);
            if (k0 + kk < NTOK) v = *(const float4*)(Vb + (size_t)(k0 + kk) * DMODEL + n4);
            *(float4*)&Vs[kk][n4] = v;
        }
        __syncthreads();
#pragma unroll
        for (int kk = 0; kk < 16; kk++) {
            float4 bv = *(const float4*)&Vs[kk][tx * 4];
            float a0 = Ps[ty * 4 + 0][kk];
            float a1 = Ps[ty * 4 + 1][kk];
            float a2 = Ps[ty * 4 + 2][kk];
            float a3 = Ps[ty * 4 + 3][kk];
            acc[0][0] += a0 * bv.x; acc[0][1] += a0 * bv.y; acc[0][2] += a0 * bv.z; acc[0][3] += a0 * bv.w;
            acc[1][0] += a1 * bv.x; acc[1][1] += a1 * bv.y; acc[1][2] += a1 * bv.z; acc[1][3] += a1 * bv.w;
            acc[2][0] += a2 * bv.x; acc[2][1] += a2 * bv.y; acc[2][2] += a2 * bv.z; acc[2][3] += a2 * bv.w;
            acc[3][0] += a3 * bv.x; acc[3][1] += a3 * bv.y; acc[3][2] += a3 * bv.z; acc[3][3] += a3 * bv.w;
        }
        __syncthreads();
    }
#pragma unroll
    for (int i = 0; i < 4; i++) {
        int m = m0 + ty * 4 + i;
        if (m >= NTOK) continue;
        float4 o4 = make_float4(acc[i][0], acc[i][1], acc[i][2], acc[i][3]);
        *(float4*)(Ob + (size_t)m * DMODEL + tx * 4) = o4;
    }
}

// ---------------- Classifier head (CLS token) ----------------
__global__ void head_kernel(const float* __restrict__ Hln, const float* __restrict__ W,
                            const float* __restrict__ bias, float* __restrict__ out)
{
    int idx = blockIdx.x * blockDim.x + threadIdx.x;
    if (idx >= BATCH * NCLS) return;
    int b = idx / NCLS, c = idx - b * NCLS;
    const float* hr = Hln + (size_t)b * NTOK * DMODEL;   // row 0 = CLS
    float s = bias[c];
#pragma unroll 4
    for (int d = 0; d < DMODEL; d++) s += hr[d] * W[(size_t)d * NCLS + c];
    out[idx] = s;
}

// ---------------- Host orchestration ----------------
extern "C" void kernel_launch(void* const* d_in, const int* in_sizes, int n_in,
                              void* d_out, int out_size)
{
    (void)in_sizes; (void)n_in; (void)out_size;
    const float* x      = (const float*)d_in[0];
    const float* proj_w = (const float*)d_in[1];
    const float* proj_b = (const float*)d_in[2];
    const float* cls_e  = (const float*)d_in[3];
    const float* pos_e  = (const float*)d_in[4];
    const float* ln1_g  = (const float*)d_in[5];
    const float* ln1_b  = (const float*)d_in[6];
    const float* qw     = (const float*)d_in[7];
    const float* qb     = (const float*)d_in[8];
    const float* kw     = (const float*)d_in[9];
    const float* kb     = (const float*)d_in[10];
    const float* vw     = (const float*)d_in[11];
    const float* vb     = (const float*)d_in[12];
    const float* ow     = (const float*)d_in[13];
    const float* ob     = (const float*)d_in[14];
    const float* ln2_g  = (const float*)d_in[15];
    const float* ln2_b  = (const float*)d_in[16];
    const float* fcw    = (const float*)d_in[17];
    const float* fcb    = (const float*)d_in[18];
    const float* pw     = (const float*)d_in[19];
    const float* pb     = (const float*)d_in[20];
    const float* lnf_g  = (const float*)d_in[21];
    const float* lnf_b  = (const float*)d_in[22];
    const float* head_w = (const float*)d_in[23];
    const float* head_b = (const float*)d_in[24];

    float *T, *E, *H, *Y, *Q, *Kp, *V, *O, *S, *Mm;
    cudaGetSymbolAddress((void**)&T,  g_T);
    cudaGetSymbolAddress((void**)&E,  g_E);
    cudaGetSymbolAddress((void**)&H,  g_H);
    cudaGetSymbolAddress((void**)&Y,  g_Y);
    cudaGetSymbolAddress((void**)&Q,  g_Q);
    cudaGetSymbolAddress((void**)&Kp, g_K);
    cudaGetSymbolAddress((void**)&V,  g_V);
    cudaGetSymbolAddress((void**)&O,  g_O);
    cudaGetSymbolAddress((void**)&S,  g_S);
    cudaGetSymbolAddress((void**)&Mm, g_M);

    // Patch embed
    patch_gather_kernel<<<(PROWS * DMODEL + 255) / 256, 256>>>(x, T);
    gemm_kernel<<<dim3(DMODEL / 128, PROWS / 128), 256>>>(
        T, proj_w, proj_b, (const float*)0, E, PROWS, DMODEL, DMODEL, 0);
    assemble_kernel<<<(TOKS * DMODEL + 255) / 256, 256>>>(E, cls_e, pos_e, H);

    const int MG = (TOKS + 127) / 128;   // 37
    for (int l = 0; l < LYRS; l++) {
        const size_t wo  = (size_t)l * DMODEL * DMODEL;
        const size_t bo  = (size_t)l * DMODEL;
        const size_t fwo = (size_t)l * DMODEL * MLPD;
        const size_t fbo = (size_t)l * MLPD;

        layernorm_kernel<<<TOKS, 256>>>(H, ln1_g + bo, ln1_b + bo, Y);
        gemm_kernel<<<dim3(6, MG), 256>>>(Y, qw + wo, qb + bo, (const float*)0, Q,  TOKS, DMODEL, DMODEL, 0);
        gemm_kernel<<<dim3(6, MG), 256>>>(Y, kw + wo, kb + bo, (const float*)0, Kp, TOKS, DMODEL, DMODEL, 0);
        gemm_kernel<<<dim3(6, MG), 256>>>(Y, vw + wo, vb + bo, (const float*)0, V,  TOKS, DMODEL, DMODEL, 0);

        attn_scores_kernel<<<dim3(10, 10, BATCH * NHEAD), 256>>>(Q, Kp, S);
        softmax_kernel<<<BATCH * NHEAD * NTOK, 128>>>(S);
        attn_out_kernel<<<dim3(1, 10, BATCH * NHEAD), 256>>>(S, V, O);

        gemm_kernel<<<dim3(6, MG), 256>>>(O, ow + wo, ob + bo, H, H, TOKS, DMODEL, DMODEL, 0);

        layernorm_kernel<<<TOKS, 256>>>(H, ln2_g + bo, ln2_b + bo, Y);
        gemm_kernel<<<dim3(MLPD / 128, MG), 256>>>(Y, fcw + fwo, fcb + fbo, (const float*)0, Mm, TOKS, MLPD, DMODEL, 1);
        gemm_kernel<<<dim3(6, MG), 256>>>(Mm, pw + fwo, pb + bo, H, H, TOKS, DMODEL, MLPD, 0);
    }

    layernorm_kernel<<<TOKS, 256>>>(H, lnf_g, lnf_b, Y);
    head_kernel<<<(BATCH * NCLS + 255) / 256, 256>>>(Y, head_w, head_b, (float*)d_out);
}